// round 4
// baseline (speedup 1.0000x reference)
#include <cuda_runtime.h>
#include <cuda_bf16.h>
#include <cstdint>

// Problem sizes
#define BB   128
#define TT   256
#define CC   384
#define HH   6
#define HSZ  64
#define MTOT (BB*TT)          // 32768
#define NQKV 1152

// Scratch (tf32 bit patterns stored as unsigned)
__device__ unsigned g_xt[MTOT*CC];        // x converted to tf32
__device__ unsigned g_wqkv[NQKV*CC];      // packed B[n][k], Wq pre-scaled by 0.125
__device__ unsigned g_wp[CC*CC];          // Wp[n][k] tf32
__device__ unsigned g_q[BB*HH*TT*HSZ];    // [B][H][T][64] tf32 (pre-scaled)
__device__ unsigned g_k[BB*HH*TT*HSZ];
__device__ unsigned g_v[BB*HH*TT*HSZ];
__device__ unsigned g_att[MTOT*CC];       // [B][T][384] tf32

__device__ __forceinline__ unsigned f2tf32(float x) {
    unsigned u;
    asm("cvt.rna.tf32.f32 %0, %1;" : "=r"(u) : "f"(x));
    return u;
}

__device__ __forceinline__ void cp_async16(unsigned* smem_dst, const unsigned* gsrc) {
    unsigned s = (unsigned)__cvta_generic_to_shared(smem_dst);
    asm volatile("cp.async.cg.shared.global [%0], [%1], 16;\n" :: "r"(s), "l"(gsrc));
}
#define CP_COMMIT() asm volatile("cp.async.commit_group;\n" ::: "memory")
#define CP_WAIT(N)  asm volatile("cp.async.wait_group %0;\n" :: "n"(N) : "memory")

__device__ __forceinline__ void mma8(float& c0, float& c1, float& c2, float& c3,
                                     unsigned a0, unsigned a1, unsigned a2, unsigned a3,
                                     unsigned b0, unsigned b1) {
    asm volatile(
        "mma.sync.aligned.m16n8k8.row.col.f32.tf32.tf32.f32 "
        "{%0,%1,%2,%3}, {%4,%5,%6,%7}, {%8,%9}, {%0,%1,%2,%3};\n"
        : "+f"(c0), "+f"(c1), "+f"(c2), "+f"(c3)
        : "r"(a0), "r"(a1), "r"(a2), "r"(a3), "r"(b0), "r"(b1));
}

// bit-reverse-3 XOR swizzle (16B-aligned: multiples of 4 words)
__device__ __forceinline__ int swz(int r) {
    return ((r & 1) << 4) | ((r & 2) << 2) | (r & 4);
}

// ---------------------------------------------------------------------------
// Prep kernels
// ---------------------------------------------------------------------------
__global__ void __launch_bounds__(256) conv_x_kernel(const float* __restrict__ x) {
    int i = (blockIdx.x * 256 + threadIdx.x) * 4;
    float4 v = *(const float4*)(x + i);
    uint4 o;
    o.x = f2tf32(v.x); o.y = f2tf32(v.y); o.z = f2tf32(v.z); o.w = f2tf32(v.w);
    *(uint4*)(g_xt + i) = o;
}

__global__ void __launch_bounds__(256) pack_w_kernel(
    const float* __restrict__ Wq, const float* __restrict__ Wk,
    const float* __restrict__ Wv, const float* __restrict__ Wp) {
    int i = blockIdx.x * 256 + threadIdx.x;
    if (i < NQKV * CC) {
        int n = i / CC, k = i - (i / CC) * CC;
        int which = n / CC;
        int rem = n - which * CC;
        int h = rem >> 6, d = rem & 63;
        const float* W = (which == 0) ? Wq : ((which == 1) ? Wk : Wv);
        float v = W[h * (CC * HSZ) + k * HSZ + d];
        if (which == 0) v *= 0.125f;
        g_wqkv[i] = f2tf32(v);
    }
    if (i < CC * CC) {
        g_wp[i] = f2tf32(Wp[i]);
    }
}

// ---------------------------------------------------------------------------
// GEMM (rebuilt): CTA 256x128, 8 warps of 64x64, BK=32, 3-stage cp.async.
// SMEM: A stages 3 x 256x36 words, B stages 3 x 128x36 words = 165888 B.
// ---------------------------------------------------------------------------
#define ASTR 36
#define A_ST_WORDS (256*ASTR)   // 9216
#define B_ST_WORDS (128*ASTR)   // 4608
#define G3_SMEM ((3*(A_ST_WORDS + B_ST_WORDS))*4)  // 165888

__device__ __forceinline__ void g3_prefetch(unsigned* smA, unsigned* smB,
                                            const unsigned* gA, const unsigned* gB,
                                            int tid) {
    #pragma unroll
    for (int it = 0; it < 8; ++it) {
        int idx = tid + it * 256;        // 0..2047 : A 256 rows x 8 chunks
        int row = idx >> 3, ch = idx & 7;
        cp_async16(smA + row * ASTR + ch * 4, gA + (size_t)row * CC + ch * 4);
    }
    #pragma unroll
    for (int it = 0; it < 4; ++it) {
        int idx = tid + it * 256;        // 0..1023 : B 128 rows x 8 chunks
        int row = idx >> 3, ch = idx & 7;
        cp_async16(smB + row * ASTR + ch * 4, gB + (size_t)row * CC + ch * 4);
    }
}

// Shared mainloop body for both GEMMs via macro-free duplication.
__global__ void __launch_bounds__(256, 1) qkv_gemm_kernel()
{
    extern __shared__ unsigned sm[];
    unsigned* smB_base = sm + 3 * A_ST_WORDS;

    const int tid  = threadIdx.x;
    const int wid  = tid >> 5;
    const int lane = tid & 31;
    const int g    = lane >> 2;
    const int qd   = lane & 3;

    const int mb = blockIdx.y * 256;
    const int nb = blockIdx.x * 128;
    const int wm = (wid >> 1) * 64;
    const int wn = (wid & 1) * 64;

    const unsigned* gA = g_xt + (size_t)mb * CC;
    const unsigned* gB = g_wqkv + (size_t)nb * CC;

    float acc[4][8][4];
    #pragma unroll
    for (int i = 0; i < 4; i++)
        #pragma unroll
        for (int j = 0; j < 8; j++)
            #pragma unroll
            for (int r = 0; r < 4; r++) acc[i][j][r] = 0.f;

    g3_prefetch(sm, smB_base, gA, gB, tid);
    CP_COMMIT();
    g3_prefetch(sm + A_ST_WORDS, smB_base + B_ST_WORDS, gA + 32, gB + 32, tid);
    CP_COMMIT();

    for (int kt = 0; kt < 12; ++kt) {
        __syncthreads();   // all warps done with compute(kt-1); safe to overwrite stage (kt+2)%3
        if (kt <= 9) {
            int s = (kt + 2) % 3;
            g3_prefetch(sm + s * A_ST_WORDS, smB_base + s * B_ST_WORDS,
                        gA + (kt + 2) * 32, gB + (kt + 2) * 32, tid);
            CP_COMMIT();
            CP_WAIT(2);
        } else if (kt == 10) {
            CP_WAIT(1);
        } else {
            CP_WAIT(0);
        }
        __syncthreads();   // group kt visible to everyone

        const unsigned* A = sm + (kt % 3) * A_ST_WORDS;
        const unsigned* B = smB_base + (kt % 3) * B_ST_WORDS;

        #pragma unroll
        for (int ks = 0; ks < 4; ++ks) {
            const int c = ks * 8 + qd;
            unsigned af[4][4];
            unsigned bf[8][2];
            #pragma unroll
            for (int im = 0; im < 4; im++) {
                int r = wm + 16 * im + g;
                af[im][0] = A[r * ASTR + c];
                af[im][1] = A[(r + 8) * ASTR + c];
                af[im][2] = A[r * ASTR + c + 4];
                af[im][3] = A[(r + 8) * ASTR + c + 4];
            }
            #pragma unroll
            for (int jn = 0; jn < 8; jn++) {
                int n = wn + 8 * jn + g;
                bf[jn][0] = B[n * ASTR + c];
                bf[jn][1] = B[n * ASTR + c + 4];
            }
            #pragma unroll
            for (int im = 0; im < 4; im++)
                #pragma unroll
                for (int jn = 0; jn < 8; jn++)
                    mma8(acc[im][jn][0], acc[im][jn][1], acc[im][jn][2], acc[im][jn][3],
                         af[im][0], af[im][1], af[im][2], af[im][3],
                         bf[jn][0], bf[jn][1]);
        }
    }

    // Epilogue: scatter tf32 bits into q/k/v [B][H][T][64]
    #pragma unroll
    for (int im = 0; im < 4; im++) {
        #pragma unroll
        for (int jn = 0; jn < 8; jn++) {
            int mg = mb + wm + 16 * im + g;
            int ng = nb + wn + 8 * jn + 2 * qd;
            int which = ng / CC;
            int rem   = ng - which * CC;
            int hh    = rem >> 6;
            int dd    = rem & 63;
            unsigned* buf = (which == 0) ? g_q : ((which == 1) ? g_k : g_v);
            int b0i = mg >> 8, t0i = mg & 255;
            uint2 v01; v01.x = f2tf32(acc[im][jn][0]); v01.y = f2tf32(acc[im][jn][1]);
            *(uint2*)(buf + ((b0i * HH + hh) * TT + t0i) * HSZ + dd) = v01;
            int mg2 = mg + 8;
            int b1i = mg2 >> 8, t1i = mg2 & 255;
            uint2 v23; v23.x = f2tf32(acc[im][jn][2]); v23.y = f2tf32(acc[im][jn][3]);
            *(uint2*)(buf + ((b1i * HH + hh) * TT + t1i) * HSZ + dd) = v23;
        }
    }
}

__global__ void __launch_bounds__(256, 1) proj_gemm_kernel(
    const float* __restrict__ bp,
    float* __restrict__ out)
{
    extern __shared__ unsigned sm[];
    unsigned* smB_base = sm + 3 * A_ST_WORDS;

    const int tid  = threadIdx.x;
    const int wid  = tid >> 5;
    const int lane = tid & 31;
    const int g    = lane >> 2;
    const int qd   = lane & 3;

    const int mb = blockIdx.y * 256;
    const int nb = blockIdx.x * 128;
    const int wm = (wid >> 1) * 64;
    const int wn = (wid & 1) * 64;

    const unsigned* gA = g_att + (size_t)mb * CC;
    const unsigned* gB = g_wp + (size_t)nb * CC;

    float acc[4][8][4];
    #pragma unroll
    for (int i = 0; i < 4; i++)
        #pragma unroll
        for (int j = 0; j < 8; j++)
            #pragma unroll
            for (int r = 0; r < 4; r++) acc[i][j][r] = 0.f;

    g3_prefetch(sm, smB_base, gA, gB, tid);
    CP_COMMIT();
    g3_prefetch(sm + A_ST_WORDS, smB_base + B_ST_WORDS, gA + 32, gB + 32, tid);
    CP_COMMIT();

    for (int kt = 0; kt < 12; ++kt) {
        __syncthreads();
        if (kt <= 9) {
            int s = (kt + 2) % 3;
            g3_prefetch(sm + s * A_ST_WORDS, smB_base + s * B_ST_WORDS,
                        gA + (kt + 2) * 32, gB + (kt + 2) * 32, tid);
            CP_COMMIT();
            CP_WAIT(2);
        } else if (kt == 10) {
            CP_WAIT(1);
        } else {
            CP_WAIT(0);
        }
        __syncthreads();

        const unsigned* A = sm + (kt % 3) * A_ST_WORDS;
        const unsigned* B = smB_base + (kt % 3) * B_ST_WORDS;

        #pragma unroll
        for (int ks = 0; ks < 4; ++ks) {
            const int c = ks * 8 + qd;
            unsigned af[4][4];
            unsigned bf[8][2];
            #pragma unroll
            for (int im = 0; im < 4; im++) {
                int r = wm + 16 * im + g;
                af[im][0] = A[r * ASTR + c];
                af[im][1] = A[(r + 8) * ASTR + c];
                af[im][2] = A[r * ASTR + c + 4];
                af[im][3] = A[(r + 8) * ASTR + c + 4];
            }
            #pragma unroll
            for (int jn = 0; jn < 8; jn++) {
                int n = wn + 8 * jn + g;
                bf[jn][0] = B[n * ASTR + c];
                bf[jn][1] = B[n * ASTR + c + 4];
            }
            #pragma unroll
            for (int im = 0; im < 4; im++)
                #pragma unroll
                for (int jn = 0; jn < 8; jn++)
                    mma8(acc[im][jn][0], acc[im][jn][1], acc[im][jn][2], acc[im][jn][3],
                         af[im][0], af[im][1], af[im][2], af[im][3],
                         bf[jn][0], bf[jn][1]);
        }
    }

    #pragma unroll
    for (int im = 0; im < 4; im++) {
        #pragma unroll
        for (int jn = 0; jn < 8; jn++) {
            int mg = mb + wm + 16 * im + g;
            int ng = nb + wn + 8 * jn + 2 * qd;
            float b0v = bp[ng], b1v = bp[ng + 1];
            float2 v01 = make_float2(acc[im][jn][0] + b0v, acc[im][jn][1] + b1v);
            *(float2*)(out + (size_t)mg * CC + ng) = v01;
            float2 v23 = make_float2(acc[im][jn][2] + b0v, acc[im][jn][3] + b1v);
            *(float2*)(out + (size_t)(mg + 8) * CC + ng) = v23;
        }
    }
}

// ---------------------------------------------------------------------------
// Attention: CTA = (bh, half) over 128 query rows, 4 warps x 32 rows,
// 128 threads, 2 CTAs/SM. KV streamed 64 rows/chunk, double-buffered.
// ---------------------------------------------------------------------------
#define AQ_WORDS 8192                 // Q region: 128 rows x 64 words
#define AST_WORDS 8192                // one stage: K 4096 + V 4096 words
#define ATTN_SMEM ((AQ_WORDS + 2*AST_WORDS) * 4)   // 98304 bytes

__global__ void __launch_bounds__(128, 2) attn_kernel()
{
    extern __shared__ unsigned sm[];
    unsigned* Qs = sm;                       // [128][64] swizzled

    const int bh   = blockIdx.x;
    const int half = 1 - blockIdx.y;         // heavy half (rows 128-255) first
    const int b    = bh / HH;
    const int h    = bh - b * HH;

    const int tid  = threadIdx.x;
    const int w    = tid >> 5;               // 0..3
    const int lane = tid & 31;
    const int g    = lane >> 2;
    const int qd   = lane & 3;

    const unsigned* qsrc = g_q + (size_t)bh * (TT * HSZ) + half * 128 * HSZ;
    const unsigned* ksrc = g_k + (size_t)bh * (TT * HSZ);
    const unsigned* vsrc = g_v + (size_t)bh * (TT * HSZ);

    // Stage Q (128 rows) + KV chunk 0
    #pragma unroll
    for (int i = 0; i < 4; i++) {
        int lin = tid + 128 * i;             // 0..511
        int r = lin >> 2, ch = lin & 3;      // 128 rows x 4 chunks? no: 64 words = 16 chunks
        (void)r; (void)ch;
    }
    #pragma unroll
    for (int i = 0; i < 4; i++) {
        int lin = tid + 128 * i;             // 0..511 : Q 128 rows x ... need 512 chunks
        int r = lin >> 2;                    // WRONG mapping placeholder
        (void)r;
    }
    // Correct staging: Q has 128 rows x 16 chunks = 2048? No: 64 words = 16 chunks of 4 words.
    // 128 rows * 16 chunks = 2048 chunks; 128 threads -> 16 each? Recompute: 64 words/row = 16
    // chunks/row only if chunk=4 words. 128*16=2048 chunks -> 16 per thread.
    #pragma unroll
    for (int i = 0; i < 16; i++) {
        int lin = tid + 128 * i;             // 0..2047
        int r = lin >> 4, ch = lin & 15;
        cp_async16(Qs + r * 64 + ((ch * 4) ^ swz(r & 7)), qsrc + r * HSZ + ch * 4);
    }
    {
        unsigned* st = sm + AQ_WORDS;        // stage 0
        #pragma unroll
        for (int i = 0; i < 8; i++) {
            int lin = tid + 128 * i;         // 0..1023
            int r = lin >> 4, ch = lin & 15;
            int phys = r * 64 + ((ch * 4) ^ swz(r & 7));
            cp_async16(st + phys,        ksrc + r * HSZ + ch * 4);
            cp_async16(st + 4096 + phys, vsrc + r * HSZ + ch * 4);
        }
    }
    CP_COMMIT();

    const int rowbase = 32 * w;                            // local row base within half
    const int jbmax_w = (half * 128 + rowbase + 31) >> 6;  // same for both 16-row groups
    const int jbmax_c = half ? 3 : 1;

    float o[2][8][4];
    #pragma unroll
    for (int i = 0; i < 2; i++)
        #pragma unroll
        for (int j = 0; j < 8; j++)
            #pragma unroll
            for (int r = 0; r < 4; r++) o[i][j][r] = 0.f;
    float row_max[2][2] = {{-1e30f, -1e30f}, {-1e30f, -1e30f}};
    float row_sum[2][2] = {{0.f, 0.f}, {0.f, 0.f}};

    const int sg = swz(g);

    for (int jb = 0; jb <= jbmax_c; ++jb) {
        CP_WAIT(0);
        __syncthreads();
        if (jb < jbmax_c) {
            unsigned* st = sm + AQ_WORDS + ((jb + 1) & 1) * AST_WORDS;
            const unsigned* kg = ksrc + (jb + 1) * 64 * HSZ;
            const unsigned* vg = vsrc + (jb + 1) * 64 * HSZ;
            #pragma unroll
            for (int i = 0; i < 8; i++) {
                int lin = tid + 128 * i;
                int r = lin >> 4, ch = lin & 15;
                int phys = r * 64 + ((ch * 4) ^ swz(r & 7));
                cp_async16(st + phys,        kg + r * HSZ + ch * 4);
                cp_async16(st + 4096 + phys, vg + r * HSZ + ch * 4);
            }
            CP_COMMIT();
        }

        if (jb <= jbmax_w) {
            const unsigned* K = sm + AQ_WORDS + (jb & 1) * AST_WORDS;
            const unsigned* V = K + 4096;

            // ---- S = Q K^T ----
            float s[2][8][4];
            #pragma unroll
            for (int i = 0; i < 2; i++)
                #pragma unroll
                for (int j = 0; j < 8; j++)
                    #pragma unroll
                    for (int r = 0; r < 4; r++) s[i][j][r] = 0.f;

            #pragma unroll
            for (int ks = 0; ks < 8; ++ks) {
                const int cs = (8 * ks + qd) ^ sg;
                unsigned af[2][4];
                #pragma unroll
                for (int im = 0; im < 2; im++) {
                    int r = rowbase + 16 * im + g;
                    af[im][0] = Qs[r * 64 + cs];
                    af[im][1] = Qs[(r + 8) * 64 + cs];
                    af[im][2] = Qs[r * 64 + (cs ^ 4)];
                    af[im][3] = Qs[(r + 8) * 64 + (cs ^ 4)];
                }
                #pragma unroll
                for (int jn = 0; jn < 8; jn++) {
                    unsigned b0 = K[(8 * jn + g) * 64 + cs];
                    unsigned b1 = K[(8 * jn + g) * 64 + (cs ^ 4)];
                    #pragma unroll
                    for (int im = 0; im < 2; im++)
                        mma8(s[im][jn][0], s[im][jn][1], s[im][jn][2], s[im][jn][3],
                             af[im][0], af[im][1], af[im][2], af[im][3], b0, b1);
                }
            }

            // ---- causal mask + online softmax ----
            #pragma unroll
            for (int im = 0; im < 2; im++) {
                #pragma unroll
                for (int hf = 0; hf < 2; hf++) {
                    int trow = half * 128 + rowbase + 16 * im + 8 * hf + g;
                    float rmax = -1e30f;
                    #pragma unroll
                    for (int jn = 0; jn < 8; jn++) {
                        #pragma unroll
                        for (int e = 0; e < 2; e++) {
                            int col = jb * 64 + 8 * jn + 2 * qd + e;
                            float v = s[im][jn][2 * hf + e];
                            if (col > trow) v = -1e30f;
                            s[im][jn][2 * hf + e] = v;
                            rmax = fmaxf(rmax, v);
                        }
                    }
                    rmax = fmaxf(rmax, __shfl_xor_sync(0xffffffffu, rmax, 1));
                    rmax = fmaxf(rmax, __shfl_xor_sync(0xffffffffu, rmax, 2));
                    float mnew = fmaxf(row_max[im][hf], rmax);
                    float corr = __expf(row_max[im][hf] - mnew);
                    row_max[im][hf] = mnew;
                    float psum = 0.f;
                    #pragma unroll
                    for (int jn = 0; jn < 8; jn++) {
                        #pragma unroll
                        for (int e = 0; e < 2; e++) {
                            float p = __expf(s[im][jn][2 * hf + e] - mnew);
                            s[im][jn][2 * hf + e] = p;
                            psum += p;
                        }
                    }
                    psum += __shfl_xor_sync(0xffffffffu, psum, 1);
                    psum += __shfl_xor_sync(0xffffffffu, psum, 2);
                    row_sum[im][hf] = row_sum[im][hf] * corr + psum;
                    #pragma unroll
                    for (int jn = 0; jn < 8; jn++) {
                        o[im][jn][2 * hf + 0] *= corr;
                        o[im][jn][2 * hf + 1] *= corr;
                    }
                }
            }

            // ---- O += P V ----
            const int src1 = 4 * g + (qd >> 1);
            const int src2 = src1 + 2;
            const bool oddq = (qd & 1);
            const int svq0 = swz(qd), svq1 = swz(qd + 4);
            #pragma unroll
            for (int ks = 0; ks < 8; ++ks) {
                unsigned pa[2][4];
                #pragma unroll
                for (int im = 0; im < 2; im++) {
                    float v00 = __shfl_sync(0xffffffffu, s[im][ks][0], src1);
                    float v01 = __shfl_sync(0xffffffffu, s[im][ks][1], src1);
                    float v20 = __shfl_sync(0xffffffffu, s[im][ks][2], src1);
                    float v21 = __shfl_sync(0xffffffffu, s[im][ks][3], src1);
                    float v40 = __shfl_sync(0xffffffffu, s[im][ks][0], src2);
                    float v41 = __shfl_sync(0xffffffffu, s[im][ks][1], src2);
                    float v60 = __shfl_sync(0xffffffffu, s[im][ks][2], src2);
                    float v61 = __shfl_sync(0xffffffffu, s[im][ks][3], src2);
                    pa[im][0] = f2tf32(oddq ? v01 : v00);
                    pa[im][1] = f2tf32(oddq ? v21 : v20);
                    pa[im][2] = f2tf32(oddq ? v41 : v40);
                    pa[im][3] = f2tf32(oddq ? v61 : v60);
                }
                const int vr0 = (8 * ks + qd) * 64;
                const int vr1 = (8 * ks + qd + 4) * 64;
                #pragma unroll
                for (int jn = 0; jn < 8; jn++) {
                    unsigned vb0 = V[vr0 + ((8 * jn + g) ^ svq0)];
                    unsigned vb1 = V[vr1 + ((8 * jn + g) ^ svq1)];
                    #pragma unroll
                    for (int im = 0; im < 2; im++)
                        mma8(o[im][jn][0], o[im][jn][1], o[im][jn][2], o[im][jn][3],
                             pa[im][0], pa[im][1], pa[im][2], pa[im][3], vb0, vb1);
                }
            }
        }
    }

    // ---- normalize + store tf32 bits to g_att [B][T][384] ----
    #pragma unroll
    for (int im = 0; im < 2; im++) {
        float inv0 = 1.0f / row_sum[im][0];
        float inv1 = 1.0f / row_sum[im][1];
        int trow = half * 128 + rowbase + 16 * im + g;
        #pragma unroll
        for (int jn = 0; jn < 8; jn++) {
            int dd = 8 * jn + 2 * qd;
            uint2 v01; v01.x = f2tf32(o[im][jn][0] * inv0); v01.y = f2tf32(o[im][jn][1] * inv0);
            *(uint2*)(g_att + (size_t)(b * TT + trow) * CC + h * HSZ + dd) = v01;
            uint2 v23; v23.x = f2tf32(o[im][jn][2] * inv1); v23.y = f2tf32(o[im][jn][3] * inv1);
            *(uint2*)(g_att + (size_t)(b * TT + trow + 8) * CC + h * HSZ + dd) = v23;
        }
    }
}

// ---------------------------------------------------------------------------
extern "C" void kernel_launch(void* const* d_in, const int* in_sizes, int n_in,
                              void* d_out, int out_size)
{
    const float* x  = (const float*)d_in[0];
    const float* Wq = (const float*)d_in[1];
    const float* Wk = (const float*)d_in[2];
    const float* Wv = (const float*)d_in[3];
    const float* Wp = (const float*)d_in[4];
    const float* bp = (const float*)d_in[5];
    float* out = (float*)d_out;

    static bool attr_set = false;
    if (!attr_set) {
        cudaFuncSetAttribute(qkv_gemm_kernel,  cudaFuncAttributeMaxDynamicSharedMemorySize, G3_SMEM);
        cudaFuncSetAttribute(proj_gemm_kernel, cudaFuncAttributeMaxDynamicSharedMemorySize, G3_SMEM);
        cudaFuncSetAttribute(attn_kernel,      cudaFuncAttributeMaxDynamicSharedMemorySize, ATTN_SMEM);
        attr_set = true;
    }

    conv_x_kernel<<<MTOT * CC / (256 * 4), 256>>>(x);
    pack_w_kernel<<<(NQKV * CC + 255) / 256, 256>>>(Wq, Wk, Wv, Wp);
    qkv_gemm_kernel<<<dim3(9, 128), 256, G3_SMEM>>>();
    attn_kernel<<<dim3(BB * HH, 2), 128, ATTN_SMEM>>>();
    proj_gemm_kernel<<<dim3(3, 128), 256, G3_SMEM>>>(bp, out);
}

// round 6
// speedup vs baseline: 1.8020x; 1.8020x over previous
#include <cuda_runtime.h>
#include <cuda_fp16.h>
#include <cstdint>

// Problem sizes
#define BB   128
#define TT   256
#define CC   384
#define HH   6
#define HSZ  64
#define MTOT (BB*TT)          // 32768
#define NQKV 1152
#define CW   192              // CC/2 half2-words per row

// Scratch: fp16 data stored as half2 packed in unsigned words
__device__ __align__(16) unsigned g_xh[MTOT*CW];        // x fp16
__device__ __align__(16) unsigned g_wqkvh[NQKV*CW];     // B[n][k] fp16, Wq pre-scaled
__device__ __align__(16) unsigned g_wph[CC*CW];         // Wp[n][k] fp16
__device__ __align__(16) unsigned g_qh[BB*HH*TT*32];    // [B][H][T][64] fp16 (pre-scaled)
__device__ __align__(16) unsigned g_kh[BB*HH*TT*32];
__device__ __align__(16) unsigned g_vh[BB*HH*TT*32];
__device__ __align__(16) unsigned g_atth[MTOT*CW];      // [B][T][384] fp16

__device__ __forceinline__ unsigned packh2(float lo, float hi) {
    unsigned u;
    asm("cvt.rn.f16x2.f32 %0, %1, %2;" : "=r"(u) : "f"(hi), "f"(lo));
    return u;
}

__device__ __forceinline__ void cp_async16(unsigned* smem_dst, const unsigned* gsrc) {
    unsigned s = (unsigned)__cvta_generic_to_shared(smem_dst);
    asm volatile("cp.async.cg.shared.global [%0], [%1], 16;\n" :: "r"(s), "l"(gsrc));
}
#define CP_COMMIT() asm volatile("cp.async.commit_group;\n" ::: "memory")
#define CP_WAIT(N)  asm volatile("cp.async.wait_group %0;\n" :: "n"(N) : "memory")

// fp16 mma m16n8k16, fp32 accumulate
__device__ __forceinline__ void mma16(float& c0, float& c1, float& c2, float& c3,
                                      unsigned a0, unsigned a1, unsigned a2, unsigned a3,
                                      unsigned b0, unsigned b1) {
    asm volatile(
        "mma.sync.aligned.m16n8k16.row.col.f32.f16.f16.f32 "
        "{%0,%1,%2,%3}, {%4,%5,%6,%7}, {%8,%9}, {%0,%1,%2,%3};\n"
        : "+f"(c0), "+f"(c1), "+f"(c2), "+f"(c3)
        : "r"(a0), "r"(a1), "r"(a2), "r"(a3), "r"(b0), "r"(b1));
}

// bit-reverse-3 XOR swizzle on word index (16B granularity, bits 2-4)
__device__ __forceinline__ int swz(int r) {
    return ((r & 1) << 4) | ((r & 2) << 2) | (r & 4);
}

// ---------------------------------------------------------------------------
// Prep kernels
// ---------------------------------------------------------------------------
__global__ void __launch_bounds__(256) conv_x_kernel(const float* __restrict__ x) {
    int i = (blockIdx.x * 256 + threadIdx.x) * 8;
    float4 v0 = *(const float4*)(x + i);
    float4 v1 = *(const float4*)(x + i + 4);
    uint4 o;
    o.x = packh2(v0.x, v0.y);
    o.y = packh2(v0.z, v0.w);
    o.z = packh2(v1.x, v1.y);
    o.w = packh2(v1.z, v1.w);
    *(uint4*)(g_xh + i / 2) = o;
}

__global__ void __launch_bounds__(256) pack_w_kernel(
    const float* __restrict__ Wq, const float* __restrict__ Wk,
    const float* __restrict__ Wv, const float* __restrict__ Wp) {
    int wi = blockIdx.x * 256 + threadIdx.x;        // word index
    if (wi < NQKV * CW) {
        int n = wi / CW, kw = wi - (wi / CW) * CW;
        int which = n / CC;
        int rem = n - which * CC;
        int h = rem >> 6, d = rem & 63;
        const float* W = (which == 0) ? Wq : ((which == 1) ? Wk : Wv);
        float v0 = W[h * (CC * HSZ) + (2 * kw) * HSZ + d];
        float v1 = W[h * (CC * HSZ) + (2 * kw + 1) * HSZ + d];
        if (which == 0) { v0 *= 0.125f; v1 *= 0.125f; }
        g_wqkvh[wi] = packh2(v0, v1);
    }
    if (wi < CC * CW) {
        int n = wi / CW, kw = wi - (wi / CW) * CW;
        g_wph[wi] = packh2(Wp[n * CC + 2 * kw], Wp[n * CC + 2 * kw + 1]);
    }
}

// ---------------------------------------------------------------------------
// fp16 GEMM: CTA 128x128, 8 warps of 64x32, BK=64 halves (32 words), 2-stage.
// SMEM per stage: A 128x36 + B 128x36 words -> 2 stages = 73728 B.
// ---------------------------------------------------------------------------
#define GSTR 36
#define STGW (128*GSTR)   // 4608 words

__device__ __forceinline__ void gemm_prefetch(unsigned* smA, unsigned* smB,
                                              const unsigned* gA, const unsigned* gB,
                                              int tid) {
    #pragma unroll
    for (int it = 0; it < 4; ++it) {
        int idx = tid + it * 256;       // 0..1023: 128 rows x 8 chunks
        int row = idx >> 3, ch = idx & 7;
        cp_async16(smA + row * GSTR + ch * 4, gA + (size_t)row * CW + ch * 4);
        cp_async16(smB + row * GSTR + ch * 4, gB + (size_t)row * CW + ch * 4);
    }
}

__global__ void __launch_bounds__(256, 2) qkv_gemm_kernel()
{
    extern __shared__ unsigned sm[];
    const int tid  = threadIdx.x;
    const int wid  = tid >> 5;
    const int lane = tid & 31;
    const int g    = lane >> 2;
    const int qd   = lane & 3;

    const int mb = blockIdx.y * 128;
    const int nb = blockIdx.x * 128;
    const int wm = (wid >> 2) * 64;
    const int wn = (wid & 3) * 32;

    const unsigned* gA = g_xh + (size_t)mb * CW;
    const unsigned* gB = g_wqkvh + (size_t)nb * CW;

    float acc[4][4][4];
    #pragma unroll
    for (int i = 0; i < 4; i++)
        #pragma unroll
        for (int j = 0; j < 4; j++)
            #pragma unroll
            for (int r = 0; r < 4; r++) acc[i][j][r] = 0.f;

    gemm_prefetch(sm, sm + 2 * STGW, gA, gB, tid);
    CP_COMMIT();

    for (int kt = 0; kt < 6; ++kt) {
        if (kt < 5) {
            int s = (kt + 1) & 1;
            gemm_prefetch(sm + s * STGW, sm + 2 * STGW + s * STGW,
                          gA + (kt + 1) * 32, gB + (kt + 1) * 32, tid);
            CP_COMMIT();
            CP_WAIT(1);
        } else {
            CP_WAIT(0);
        }
        __syncthreads();

        const unsigned* A = sm + (kt & 1) * STGW;
        const unsigned* B = sm + 2 * STGW + (kt & 1) * STGW;

        #pragma unroll
        for (int ks = 0; ks < 4; ++ks) {
            unsigned af[4][4];
            unsigned bf[4][2];
            const int c = ks * 8 + qd;
            #pragma unroll
            for (int im = 0; im < 4; im++) {
                int r = wm + 16 * im + g;
                af[im][0] = A[r * GSTR + c];
                af[im][1] = A[(r + 8) * GSTR + c];
                af[im][2] = A[r * GSTR + c + 4];
                af[im][3] = A[(r + 8) * GSTR + c + 4];
            }
            #pragma unroll
            for (int jn = 0; jn < 4; jn++) {
                int n = wn + 8 * jn + g;
                bf[jn][0] = B[n * GSTR + c];
                bf[jn][1] = B[n * GSTR + c + 4];
            }
            #pragma unroll
            for (int im = 0; im < 4; im++)
                #pragma unroll
                for (int jn = 0; jn < 4; jn++)
                    mma16(acc[im][jn][0], acc[im][jn][1], acc[im][jn][2], acc[im][jn][3],
                          af[im][0], af[im][1], af[im][2], af[im][3],
                          bf[jn][0], bf[jn][1]);
        }
        __syncthreads();
    }

    // Epilogue: pack fp16 and scatter into q/k/v [B][H][T][64]
    #pragma unroll
    for (int im = 0; im < 4; im++) {
        #pragma unroll
        for (int jn = 0; jn < 4; jn++) {
            int mg = mb + wm + 16 * im + g;
            int ng = nb + wn + 8 * jn + 2 * qd;
            int which = ng / CC;
            int rem   = ng - which * CC;
            int hh    = rem >> 6;
            int dw    = (rem & 63) >> 1;
            unsigned* buf = (which == 0) ? g_qh : ((which == 1) ? g_kh : g_vh);
            int b0i = mg >> 8, t0i = mg & 255;
            buf[((b0i * HH + hh) * TT + t0i) * 32 + dw] = packh2(acc[im][jn][0], acc[im][jn][1]);
            int mg2 = mg + 8;
            int b1i = mg2 >> 8, t1i = mg2 & 255;
            buf[((b1i * HH + hh) * TT + t1i) * 32 + dw] = packh2(acc[im][jn][2], acc[im][jn][3]);
        }
    }
}

__global__ void __launch_bounds__(256, 2) proj_gemm_kernel(
    const float* __restrict__ bp,
    float* __restrict__ out)
{
    extern __shared__ unsigned sm[];
    const int tid  = threadIdx.x;
    const int wid  = tid >> 5;
    const int lane = tid & 31;
    const int g    = lane >> 2;
    const int qd   = lane & 3;

    const int mb = blockIdx.y * 128;
    const int nb = blockIdx.x * 128;
    const int wm = (wid >> 2) * 64;
    const int wn = (wid & 3) * 32;

    const unsigned* gA = g_atth + (size_t)mb * CW;
    const unsigned* gB = g_wph + (size_t)nb * CW;

    float acc[4][4][4];
    #pragma unroll
    for (int i = 0; i < 4; i++)
        #pragma unroll
        for (int j = 0; j < 4; j++)
            #pragma unroll
            for (int r = 0; r < 4; r++) acc[i][j][r] = 0.f;

    gemm_prefetch(sm, sm + 2 * STGW, gA, gB, tid);
    CP_COMMIT();

    for (int kt = 0; kt < 6; ++kt) {
        if (kt < 5) {
            int s = (kt + 1) & 1;
            gemm_prefetch(sm + s * STGW, sm + 2 * STGW + s * STGW,
                          gA + (kt + 1) * 32, gB + (kt + 1) * 32, tid);
            CP_COMMIT();
            CP_WAIT(1);
        } else {
            CP_WAIT(0);
        }
        __syncthreads();

        const unsigned* A = sm + (kt & 1) * STGW;
        const unsigned* B = sm + 2 * STGW + (kt & 1) * STGW;

        #pragma unroll
        for (int ks = 0; ks < 4; ++ks) {
            unsigned af[4][4];
            unsigned bf[4][2];
            const int c = ks * 8 + qd;
            #pragma unroll
            for (int im = 0; im < 4; im++) {
                int r = wm + 16 * im + g;
                af[im][0] = A[r * GSTR + c];
                af[im][1] = A[(r + 8) * GSTR + c];
                af[im][2] = A[r * GSTR + c + 4];
                af[im][3] = A[(r + 8) * GSTR + c + 4];
            }
            #pragma unroll
            for (int jn = 0; jn < 4; jn++) {
                int n = wn + 8 * jn + g;
                bf[jn][0] = B[n * GSTR + c];
                bf[jn][1] = B[n * GSTR + c + 4];
            }
            #pragma unroll
            for (int im = 0; im < 4; im++)
                #pragma unroll
                for (int jn = 0; jn < 4; jn++)
                    mma16(acc[im][jn][0], acc[im][jn][1], acc[im][jn][2], acc[im][jn][3],
                          af[im][0], af[im][1], af[im][2], af[im][3],
                          bf[jn][0], bf[jn][1]);
        }
        __syncthreads();
    }

    #pragma unroll
    for (int im = 0; im < 4; im++) {
        #pragma unroll
        for (int jn = 0; jn < 4; jn++) {
            int mg = mb + wm + 16 * im + g;
            int ng = nb + wn + 8 * jn + 2 * qd;
            float b0v = bp[ng], b1v = bp[ng + 1];
            float2 v01 = make_float2(acc[im][jn][0] + b0v, acc[im][jn][1] + b1v);
            *(float2*)(out + (size_t)mg * CC + ng) = v01;
            float2 v23 = make_float2(acc[im][jn][2] + b0v, acc[im][jn][3] + b1v);
            *(float2*)(out + (size_t)(mg + 8) * CC + ng) = v23;
        }
    }
}

// ---------------------------------------------------------------------------
// Attention (fp16): CTA = (bh, half), 8 warps x 16 query rows, 2 CTAs/SM.
// Q resident (128x32 words), KV streamed 64 rows/chunk double-buffered.
// P-fragment needs NO shuffles (fp16 k16 A-layout == accumulator layout).
// V B-fragments via ldmatrix.x4.trans.
// ---------------------------------------------------------------------------
#define AQ_W 4096                 // Q: 128 rows x 32 words
#define AST_W 4096                // one stage: K 2048 + V 2048 words
#define ATTN_SMEM ((AQ_W + 2*AST_W) * 4)   // 49152 bytes

__global__ void __launch_bounds__(256, 2) attn_kernel()
{
    extern __shared__ unsigned smem[];
    unsigned* Qs = smem;                     // [128][32] swizzled

    const int bh   = blockIdx.x;
    const int half = 1 - blockIdx.y;         // heavy half (rows 128-255) first
    const int b    = bh / HH;
    const int h    = bh - b * HH;

    const int tid  = threadIdx.x;
    const int w    = tid >> 5;
    const int lane = tid & 31;
    const int g    = lane >> 2;
    const int qd   = lane & 3;

    const unsigned* qsrc = g_qh + (size_t)bh * (TT * 32) + half * 128 * 32;
    const unsigned* ksrc = g_kh + (size_t)bh * (TT * 32);
    const unsigned* vsrc = g_vh + (size_t)bh * (TT * 32);

    const unsigned smb32 = (unsigned)__cvta_generic_to_shared(smem);

    // Stage Q (128 rows x 8 chunks) + KV chunk 0
    #pragma unroll
    for (int i = 0; i < 4; i++) {
        int lin = tid + 256 * i;             // 0..1023
        int r = lin >> 3, ch = lin & 7;
        cp_async16(Qs + r * 32 + ((ch * 4) ^ swz(r & 7)), qsrc + r * 32 + ch * 4);
    }
    {
        unsigned* st = smem + AQ_W;          // stage 0
        #pragma unroll
        for (int i = 0; i < 2; i++) {
            int lin = tid + 256 * i;         // 0..511
            int r = lin >> 3, ch = lin & 7;
            int phys = r * 32 + ((ch * 4) ^ swz(r & 7));
            cp_async16(st + phys,        ksrc + r * 32 + ch * 4);
            cp_async16(st + 2048 + phys, vsrc + r * 32 + ch * 4);
        }
    }
    CP_COMMIT();

    const int jbmax_w = (half * 128 + 16 * w + 15) >> 6;
    const int jbmax_c = half ? 3 : 1;

    float o[8][4];
    #pragma unroll
    for (int j = 0; j < 8; j++)
        #pragma unroll
        for (int r = 0; r < 4; r++) o[j][r] = 0.f;
    float row_max[2] = {-1e30f, -1e30f};
    float row_sum[2] = {0.f, 0.f};

    const int r0 = 16 * w + g;               // local Q row
    const int sg = swz(g);

    // per-lane ldmatrix address components (V: trans)
    const int lmat = lane >> 3;              // 0..3
    const int lr8  = lane & 7;
    const int vrow_off = ((lmat & 1) << 3) + lr8;    // + 16*ks
    const int vswz = swz(lr8);

    for (int jb = 0; jb <= jbmax_c; ++jb) {
        CP_WAIT(0);
        __syncthreads();
        if (jb < jbmax_c) {
            unsigned* st = smem + AQ_W + ((jb + 1) & 1) * AST_W;
            const unsigned* kg = ksrc + (jb + 1) * 64 * 32;
            const unsigned* vg = vsrc + (jb + 1) * 64 * 32;
            #pragma unroll
            for (int i = 0; i < 2; i++) {
                int lin = tid + 256 * i;
                int r = lin >> 3, ch = lin & 7;
                int phys = r * 32 + ((ch * 4) ^ swz(r & 7));
                cp_async16(st + phys,        kg + r * 32 + ch * 4);
                cp_async16(st + 2048 + phys, vg + r * 32 + ch * 4);
            }
            CP_COMMIT();
        }

        if (jb <= jbmax_w) {
            const unsigned* K = smem + AQ_W + (jb & 1) * AST_W;
            const unsigned vb32 = smb32 + (AQ_W + (jb & 1) * AST_W + 2048) * 4;

            // ---- S = Q K^T  (4 ksteps of k16) ----
            float s[8][4];
            #pragma unroll
            for (int j = 0; j < 8; j++)
                #pragma unroll
                for (int r = 0; r < 4; r++) s[j][r] = 0.f;

            #pragma unroll
            for (int ks = 0; ks < 4; ++ks) {
                const int cs = (8 * ks + qd) ^ sg;
                unsigned a0 = Qs[r0 * 32 + cs];
                unsigned a1 = Qs[(r0 + 8) * 32 + cs];
                unsigned a2 = Qs[r0 * 32 + (cs ^ 4)];
                unsigned a3 = Qs[(r0 + 8) * 32 + (cs ^ 4)];
                #pragma unroll
                for (int jn = 0; jn < 8; jn++) {
                    unsigned b0 = K[(8 * jn + g) * 32 + cs];
                    unsigned b1 = K[(8 * jn + g) * 32 + (cs ^ 4)];
                    mma16(s[jn][0], s[jn][1], s[jn][2], s[jn][3],
                          a0, a1, a2, a3, b0, b1);
                }
            }

            // ---- causal mask + online softmax ----
            #pragma unroll
            for (int hf = 0; hf < 2; hf++) {
                int trow = half * 128 + 16 * w + 8 * hf + g;
                float rmax = -1e30f;
                #pragma unroll
                for (int jn = 0; jn < 8; jn++) {
                    #pragma unroll
                    for (int e = 0; e < 2; e++) {
                        int col = jb * 64 + 8 * jn + 2 * qd + e;
                        float v = s[jn][2 * hf + e];
                        if (col > trow) v = -1e30f;
                        s[jn][2 * hf + e] = v;
                        rmax = fmaxf(rmax, v);
                    }
                }
                rmax = fmaxf(rmax, __shfl_xor_sync(0xffffffffu, rmax, 1));
                rmax = fmaxf(rmax, __shfl_xor_sync(0xffffffffu, rmax, 2));
                float mnew = fmaxf(row_max[hf], rmax);
                float corr = __expf(row_max[hf] - mnew);
                row_max[hf] = mnew;
                float psum = 0.f;
                #pragma unroll
                for (int jn = 0; jn < 8; jn++) {
                    #pragma unroll
                    for (int e = 0; e < 2; e++) {
                        float p = __expf(s[jn][2 * hf + e] - mnew);
                        s[jn][2 * hf + e] = p;
                        psum += p;
                    }
                }
                psum += __shfl_xor_sync(0xffffffffu, psum, 1);
                psum += __shfl_xor_sync(0xffffffffu, psum, 2);
                row_sum[hf] = row_sum[hf] * corr + psum;
                #pragma unroll
                for (int jn = 0; jn < 8; jn++) {
                    o[jn][2 * hf + 0] *= corr;
                    o[jn][2 * hf + 1] *= corr;
                }
            }

            // ---- O += P V  (P fragment = repacked accumulator, no shuffles) ----
            #pragma unroll
            for (int ks = 0; ks < 4; ++ks) {
                unsigned pa0 = packh2(s[2 * ks][0],     s[2 * ks][1]);
                unsigned pa1 = packh2(s[2 * ks][2],     s[2 * ks][3]);
                unsigned pa2 = packh2(s[2 * ks + 1][0], s[2 * ks + 1][1]);
                unsigned pa3 = packh2(s[2 * ks + 1][2], s[2 * ks + 1][3]);

                // V B-fragments via ldmatrix.x4.trans, 2 jn per call
                unsigned vb[4][4];
                #pragma unroll
                for (int jnp = 0; jnp < 4; jnp++) {
                    int vrow = 16 * ks + vrow_off;
                    int wc = (4 * (2 * jnp + (lmat >> 1))) ^ vswz;
                    unsigned addr = vb32 + (vrow * 32 + wc) * 4;
                    asm volatile(
                        "ldmatrix.sync.aligned.m8n8.x4.trans.shared.b16 {%0,%1,%2,%3}, [%4];"
                        : "=r"(vb[jnp][0]), "=r"(vb[jnp][1]), "=r"(vb[jnp][2]), "=r"(vb[jnp][3])
                        : "r"(addr));
                }
                #pragma unroll
                for (int jn = 0; jn < 8; jn++) {
                    unsigned b0 = vb[jn >> 1][(jn & 1) * 2];
                    unsigned b1 = vb[jn >> 1][(jn & 1) * 2 + 1];
                    mma16(o[jn][0], o[jn][1], o[jn][2], o[jn][3],
                          pa0, pa1, pa2, pa3, b0, b1);
                }
            }
        }
    }

    // ---- normalize + store fp16 to g_atth [B][T][384] ----
    float inv0 = 1.0f / row_sum[0];
    float inv1 = 1.0f / row_sum[1];
    int trow = half * 128 + 16 * w + g;
    #pragma unroll
    for (int jn = 0; jn < 8; jn++) {
        int wdd = h * 32 + 4 * jn + qd;
        g_atth[(size_t)(b * TT + trow) * CW + wdd]       = packh2(o[jn][0] * inv0, o[jn][1] * inv0);
        g_atth[(size_t)(b * TT + trow + 8) * CW + wdd]   = packh2(o[jn][2] * inv1, o[jn][3] * inv1);
    }
}

// ---------------------------------------------------------------------------
extern "C" void kernel_launch(void* const* d_in, const int* in_sizes, int n_in,
                              void* d_out, int out_size)
{
    const float* x  = (const float*)d_in[0];
    const float* Wq = (const float*)d_in[1];
    const float* Wk = (const float*)d_in[2];
    const float* Wv = (const float*)d_in[3];
    const float* Wp = (const float*)d_in[4];
    const float* bp = (const float*)d_in[5];
    float* out = (float*)d_out;

    static bool attr_set = false;
    const int gemm_smem = 4 * STGW * 4;     // 73728 B
    if (!attr_set) {
        cudaFuncSetAttribute(qkv_gemm_kernel,  cudaFuncAttributeMaxDynamicSharedMemorySize, gemm_smem);
        cudaFuncSetAttribute(proj_gemm_kernel, cudaFuncAttributeMaxDynamicSharedMemorySize, gemm_smem);
        cudaFuncSetAttribute(attn_kernel,      cudaFuncAttributeMaxDynamicSharedMemorySize, ATTN_SMEM);
        attr_set = true;
    }

    conv_x_kernel<<<MTOT * CC / (256 * 8), 256>>>(x);
    pack_w_kernel<<<(NQKV * CW + 255) / 256, 256>>>(Wq, Wk, Wv, Wp);
    qkv_gemm_kernel<<<dim3(9, 256), 256, gemm_smem>>>();
    attn_kernel<<<dim3(BB * HH, 2), 256, ATTN_SMEM>>>();
    proj_gemm_kernel<<<dim3(3, 256), 256, gemm_smem>>>(bp, out);
}

// round 7
// speedup vs baseline: 1.8280x; 1.0144x over previous
#include <cuda_runtime.h>
#include <cuda_fp16.h>
#include <cstdint>

// Problem sizes
#define BB   128
#define TT   256
#define CC   384
#define HH   6
#define HSZ  64
#define MTOT (BB*TT)          // 32768
#define NQKV 1152
#define CW   192              // CC/2 half2-words per row

// Scratch: fp16 data stored as half2 packed in unsigned words
__device__ __align__(16) unsigned g_xh[MTOT*CW];        // x fp16
__device__ __align__(16) unsigned g_wqkvh[NQKV*CW];     // B[n][k] fp16, Wq pre-scaled
__device__ __align__(16) unsigned g_wph[CC*CW];         // Wp[n][k] fp16
__device__ __align__(16) unsigned g_qh[BB*HH*TT*32];    // [B][H][T][64] fp16 (pre-scaled)
__device__ __align__(16) unsigned g_kh[BB*HH*TT*32];
__device__ __align__(16) unsigned g_vh[BB*HH*TT*32];
__device__ __align__(16) unsigned g_atth[MTOT*CW];      // [B][T][384] fp16

#define QSCALE 0.1803368801111204f   // 0.125 * log2(e)

__device__ __forceinline__ unsigned packh2(float lo, float hi) {
    unsigned u;
    asm("cvt.rn.f16x2.f32 %0, %1, %2;" : "=r"(u) : "f"(hi), "f"(lo));
    return u;
}

__device__ __forceinline__ float ex2f(float x) {
    float y;
    asm("ex2.approx.f32 %0, %1;" : "=f"(y) : "f"(x));
    return y;
}

__device__ __forceinline__ void cp_async16(unsigned* smem_dst, const unsigned* gsrc) {
    unsigned s = (unsigned)__cvta_generic_to_shared(smem_dst);
    asm volatile("cp.async.cg.shared.global [%0], [%1], 16;\n" :: "r"(s), "l"(gsrc));
}
#define CP_COMMIT() asm volatile("cp.async.commit_group;\n" ::: "memory")
#define CP_WAIT(N)  asm volatile("cp.async.wait_group %0;\n" :: "n"(N) : "memory")

// fp16 mma m16n8k16, fp32 accumulate
__device__ __forceinline__ void mma16(float& c0, float& c1, float& c2, float& c3,
                                      unsigned a0, unsigned a1, unsigned a2, unsigned a3,
                                      unsigned b0, unsigned b1) {
    asm volatile(
        "mma.sync.aligned.m16n8k16.row.col.f32.f16.f16.f32 "
        "{%0,%1,%2,%3}, {%4,%5,%6,%7}, {%8,%9}, {%0,%1,%2,%3};\n"
        : "+f"(c0), "+f"(c1), "+f"(c2), "+f"(c3)
        : "r"(a0), "r"(a1), "r"(a2), "r"(a3), "r"(b0), "r"(b1));
}

// bit-reverse-3 XOR swizzle on word index (16B granularity, bits 2-4)
__device__ __forceinline__ int swz(int r) {
    return ((r & 1) << 4) | ((r & 2) << 2) | (r & 4);
}

// ---------------------------------------------------------------------------
// Merged prep kernel: blocks [0, NCONV) convert x; blocks [NCONV, ..) pack W.
// ---------------------------------------------------------------------------
#define NCONV (MTOT * CC / (256 * 8))      // 6144
#define NPACK ((NQKV * CW + 255) / 256)    // 864

__global__ void __launch_bounds__(256) prep_kernel(
    const float* __restrict__ x,
    const float* __restrict__ Wq, const float* __restrict__ Wk,
    const float* __restrict__ Wv, const float* __restrict__ Wp)
{
    if (blockIdx.x < NCONV) {
        int i = (blockIdx.x * 256 + threadIdx.x) * 8;
        float4 v0 = *(const float4*)(x + i);
        float4 v1 = *(const float4*)(x + i + 4);
        uint4 o;
        o.x = packh2(v0.x, v0.y);
        o.y = packh2(v0.z, v0.w);
        o.z = packh2(v1.x, v1.y);
        o.w = packh2(v1.z, v1.w);
        *(uint4*)(g_xh + i / 2) = o;
        return;
    }
    int wi = (blockIdx.x - NCONV) * 256 + threadIdx.x;   // word index
    if (wi < NQKV * CW) {
        int n = wi / CW, kw = wi - (wi / CW) * CW;
        int which = n / CC;
        int rem = n - which * CC;
        int h = rem >> 6, d = rem & 63;
        const float* W = (which == 0) ? Wq : ((which == 1) ? Wk : Wv);
        float v0 = W[h * (CC * HSZ) + (2 * kw) * HSZ + d];
        float v1 = W[h * (CC * HSZ) + (2 * kw + 1) * HSZ + d];
        if (which == 0) { v0 *= QSCALE; v1 *= QSCALE; }
        g_wqkvh[wi] = packh2(v0, v1);
    }
    if (wi < CC * CW) {
        int n = wi / CW, kw = wi - (wi / CW) * CW;
        g_wph[wi] = packh2(Wp[n * CC + 2 * kw], Wp[n * CC + 2 * kw + 1]);
    }
}

// ---------------------------------------------------------------------------
// fp16 GEMM: CTA 128x128, 8 warps of 64x32, BK=64 halves (32 words), 2-stage.
// ---------------------------------------------------------------------------
#define GSTR 36
#define STGW (128*GSTR)   // 4608 words

__device__ __forceinline__ void gemm_prefetch(unsigned* smA, unsigned* smB,
                                              const unsigned* gA, const unsigned* gB,
                                              int tid) {
    #pragma unroll
    for (int it = 0; it < 4; ++it) {
        int idx = tid + it * 256;       // 0..1023: 128 rows x 8 chunks
        int row = idx >> 3, ch = idx & 7;
        cp_async16(smA + row * GSTR + ch * 4, gA + (size_t)row * CW + ch * 4);
        cp_async16(smB + row * GSTR + ch * 4, gB + (size_t)row * CW + ch * 4);
    }
}

__global__ void __launch_bounds__(256, 2) qkv_gemm_kernel()
{
    extern __shared__ unsigned sm[];
    const int tid  = threadIdx.x;
    const int wid  = tid >> 5;
    const int lane = tid & 31;
    const int g    = lane >> 2;
    const int qd   = lane & 3;

    const int mb = blockIdx.y * 128;
    const int nb = blockIdx.x * 128;
    const int wm = (wid >> 2) * 64;
    const int wn = (wid & 3) * 32;

    const unsigned* gA = g_xh + (size_t)mb * CW;
    const unsigned* gB = g_wqkvh + (size_t)nb * CW;

    float acc[4][4][4];
    #pragma unroll
    for (int i = 0; i < 4; i++)
        #pragma unroll
        for (int j = 0; j < 4; j++)
            #pragma unroll
            for (int r = 0; r < 4; r++) acc[i][j][r] = 0.f;

    gemm_prefetch(sm, sm + 2 * STGW, gA, gB, tid);
    CP_COMMIT();

    for (int kt = 0; kt < 6; ++kt) {
        if (kt < 5) {
            int s = (kt + 1) & 1;
            gemm_prefetch(sm + s * STGW, sm + 2 * STGW + s * STGW,
                          gA + (kt + 1) * 32, gB + (kt + 1) * 32, tid);
            CP_COMMIT();
            CP_WAIT(1);
        } else {
            CP_WAIT(0);
        }
        __syncthreads();

        const unsigned* A = sm + (kt & 1) * STGW;
        const unsigned* B = sm + 2 * STGW + (kt & 1) * STGW;

        #pragma unroll
        for (int ks = 0; ks < 4; ++ks) {
            unsigned af[4][4];
            unsigned bf[4][2];
            const int c = ks * 8 + qd;
            #pragma unroll
            for (int im = 0; im < 4; im++) {
                int r = wm + 16 * im + g;
                af[im][0] = A[r * GSTR + c];
                af[im][1] = A[(r + 8) * GSTR + c];
                af[im][2] = A[r * GSTR + c + 4];
                af[im][3] = A[(r + 8) * GSTR + c + 4];
            }
            #pragma unroll
            for (int jn = 0; jn < 4; jn++) {
                int n = wn + 8 * jn + g;
                bf[jn][0] = B[n * GSTR + c];
                bf[jn][1] = B[n * GSTR + c + 4];
            }
            #pragma unroll
            for (int im = 0; im < 4; im++)
                #pragma unroll
                for (int jn = 0; jn < 4; jn++)
                    mma16(acc[im][jn][0], acc[im][jn][1], acc[im][jn][2], acc[im][jn][3],
                          af[im][0], af[im][1], af[im][2], af[im][3],
                          bf[jn][0], bf[jn][1]);
        }
        __syncthreads();
    }

    // Epilogue: pack fp16 and scatter into q/k/v [B][H][T][64]
    #pragma unroll
    for (int im = 0; im < 4; im++) {
        #pragma unroll
        for (int jn = 0; jn < 4; jn++) {
            int mg = mb + wm + 16 * im + g;
            int ng = nb + wn + 8 * jn + 2 * qd;
            int which = ng / CC;
            int rem   = ng - which * CC;
            int hh    = rem >> 6;
            int dw    = (rem & 63) >> 1;
            unsigned* buf = (which == 0) ? g_qh : ((which == 1) ? g_kh : g_vh);
            int b0i = mg >> 8, t0i = mg & 255;
            buf[((b0i * HH + hh) * TT + t0i) * 32 + dw] = packh2(acc[im][jn][0], acc[im][jn][1]);
            int mg2 = mg + 8;
            int b1i = mg2 >> 8, t1i = mg2 & 255;
            buf[((b1i * HH + hh) * TT + t1i) * 32 + dw] = packh2(acc[im][jn][2], acc[im][jn][3]);
        }
    }
}

__global__ void __launch_bounds__(256, 2) proj_gemm_kernel(
    const float* __restrict__ bp,
    float* __restrict__ out)
{
    extern __shared__ unsigned sm[];
    const int tid  = threadIdx.x;
    const int wid  = tid >> 5;
    const int lane = tid & 31;
    const int g    = lane >> 2;
    const int qd   = lane & 3;

    const int mb = blockIdx.y * 128;
    const int nb = blockIdx.x * 128;
    const int wm = (wid >> 2) * 64;
    const int wn = (wid & 3) * 32;

    const unsigned* gA = g_atth + (size_t)mb * CW;
    const unsigned* gB = g_wph + (size_t)nb * CW;

    float acc[4][4][4];
    #pragma unroll
    for (int i = 0; i < 4; i++)
        #pragma unroll
        for (int j = 0; j < 4; j++)
            #pragma unroll
            for (int r = 0; r < 4; r++) acc[i][j][r] = 0.f;

    gemm_prefetch(sm, sm + 2 * STGW, gA, gB, tid);
    CP_COMMIT();

    for (int kt = 0; kt < 6; ++kt) {
        if (kt < 5) {
            int s = (kt + 1) & 1;
            gemm_prefetch(sm + s * STGW, sm + 2 * STGW + s * STGW,
                          gA + (kt + 1) * 32, gB + (kt + 1) * 32, tid);
            CP_COMMIT();
            CP_WAIT(1);
        } else {
            CP_WAIT(0);
        }
        __syncthreads();

        const unsigned* A = sm + (kt & 1) * STGW;
        const unsigned* B = sm + 2 * STGW + (kt & 1) * STGW;

        #pragma unroll
        for (int ks = 0; ks < 4; ++ks) {
            unsigned af[4][4];
            unsigned bf[4][2];
            const int c = ks * 8 + qd;
            #pragma unroll
            for (int im = 0; im < 4; im++) {
                int r = wm + 16 * im + g;
                af[im][0] = A[r * GSTR + c];
                af[im][1] = A[(r + 8) * GSTR + c];
                af[im][2] = A[r * GSTR + c + 4];
                af[im][3] = A[(r + 8) * GSTR + c + 4];
            }
            #pragma unroll
            for (int jn = 0; jn < 4; jn++) {
                int n = wn + 8 * jn + g;
                bf[jn][0] = B[n * GSTR + c];
                bf[jn][1] = B[n * GSTR + c + 4];
            }
            #pragma unroll
            for (int im = 0; im < 4; im++)
                #pragma unroll
                for (int jn = 0; jn < 4; jn++)
                    mma16(acc[im][jn][0], acc[im][jn][1], acc[im][jn][2], acc[im][jn][3],
                          af[im][0], af[im][1], af[im][2], af[im][3],
                          bf[jn][0], bf[jn][1]);
        }
        __syncthreads();
    }

    #pragma unroll
    for (int im = 0; im < 4; im++) {
        #pragma unroll
        for (int jn = 0; jn < 4; jn++) {
            int mg = mb + wm + 16 * im + g;
            int ng = nb + wn + 8 * jn + 2 * qd;
            float b0v = bp[ng], b1v = bp[ng + 1];
            float2 v01 = make_float2(acc[im][jn][0] + b0v, acc[im][jn][1] + b1v);
            *(float2*)(out + (size_t)mg * CC + ng) = v01;
            float2 v23 = make_float2(acc[im][jn][2] + b0v, acc[im][jn][3] + b1v);
            *(float2*)(out + (size_t)(mg + 8) * CC + ng) = v23;
        }
    }
}

// ---------------------------------------------------------------------------
// Attention (fp16): CTA = (bh, half), 8 warps x 16 query rows, 2 CTAs/SM.
// Scores arrive pre-scaled by log2(e); softmax uses raw ex2.
// Mask loop skipped on fully-visible blocks (warp-uniform branch).
// ---------------------------------------------------------------------------
#define AQ_W 4096                 // Q: 128 rows x 32 words
#define AST_W 4096                // one stage: K 2048 + V 2048 words
#define ATTN_SMEM ((AQ_W + 2*AST_W) * 4)   // 49152 bytes

__global__ void __launch_bounds__(256, 2) attn_kernel()
{
    extern __shared__ unsigned smem[];
    unsigned* Qs = smem;                     // [128][32] swizzled

    const int bh   = blockIdx.x;
    const int half = 1 - blockIdx.y;         // heavy half (rows 128-255) first
    const int b    = bh / HH;
    const int h    = bh - b * HH;

    const int tid  = threadIdx.x;
    const int w    = tid >> 5;
    const int lane = tid & 31;
    const int g    = lane >> 2;
    const int qd   = lane & 3;

    const unsigned* qsrc = g_qh + (size_t)bh * (TT * 32) + half * 128 * 32;
    const unsigned* ksrc = g_kh + (size_t)bh * (TT * 32);
    const unsigned* vsrc = g_vh + (size_t)bh * (TT * 32);

    const unsigned smb32 = (unsigned)__cvta_generic_to_shared(smem);

    // Stage Q (128 rows x 8 chunks) + KV chunk 0
    #pragma unroll
    for (int i = 0; i < 4; i++) {
        int lin = tid + 256 * i;             // 0..1023
        int r = lin >> 3, ch = lin & 7;
        cp_async16(Qs + r * 32 + ((ch * 4) ^ swz(r & 7)), qsrc + r * 32 + ch * 4);
    }
    {
        unsigned* st = smem + AQ_W;          // stage 0
        #pragma unroll
        for (int i = 0; i < 2; i++) {
            int lin = tid + 256 * i;         // 0..511
            int r = lin >> 3, ch = lin & 7;
            int phys = r * 32 + ((ch * 4) ^ swz(r & 7));
            cp_async16(st + phys,        ksrc + r * 32 + ch * 4);
            cp_async16(st + 2048 + phys, vsrc + r * 32 + ch * 4);
        }
    }
    CP_COMMIT();

    const int wminrow = half * 128 + 16 * w;
    const int jbmax_w = (wminrow + 15) >> 6;
    const int jbmax_c = half ? 3 : 1;

    float o[8][4];
    #pragma unroll
    for (int j = 0; j < 8; j++)
        #pragma unroll
        for (int r = 0; r < 4; r++) o[j][r] = 0.f;
    float row_max[2] = {-1e30f, -1e30f};
    float row_sum[2] = {0.f, 0.f};

    const int r0 = 16 * w + g;               // local Q row
    const int sg = swz(g);

    // per-lane ldmatrix address components (V: trans)
    const int lmat = lane >> 3;              // 0..3
    const int lr8  = lane & 7;
    const int vrow_off = ((lmat & 1) << 3) + lr8;    // + 16*ks
    const int vswz = swz(lr8);

    for (int jb = 0; jb <= jbmax_c; ++jb) {
        CP_WAIT(0);
        __syncthreads();
        if (jb < jbmax_c) {
            unsigned* st = smem + AQ_W + ((jb + 1) & 1) * AST_W;
            const unsigned* kg = ksrc + (jb + 1) * 64 * 32;
            const unsigned* vg = vsrc + (jb + 1) * 64 * 32;
            #pragma unroll
            for (int i = 0; i < 2; i++) {
                int lin = tid + 256 * i;
                int r = lin >> 3, ch = lin & 7;
                int phys = r * 32 + ((ch * 4) ^ swz(r & 7));
                cp_async16(st + phys,        kg + r * 32 + ch * 4);
                cp_async16(st + 2048 + phys, vg + r * 32 + ch * 4);
            }
            CP_COMMIT();
        }

        if (jb <= jbmax_w) {
            const unsigned* K = smem + AQ_W + (jb & 1) * AST_W;
            const unsigned vb32 = smb32 + (AQ_W + (jb & 1) * AST_W + 2048) * 4;

            // ---- S = Q K^T  (4 ksteps of k16) ----
            float s[8][4];
            #pragma unroll
            for (int j = 0; j < 8; j++)
                #pragma unroll
                for (int r = 0; r < 4; r++) s[j][r] = 0.f;

            #pragma unroll
            for (int ks = 0; ks < 4; ++ks) {
                const int cs = (8 * ks + qd) ^ sg;
                unsigned a0 = Qs[r0 * 32 + cs];
                unsigned a1 = Qs[(r0 + 8) * 32 + cs];
                unsigned a2 = Qs[r0 * 32 + (cs ^ 4)];
                unsigned a3 = Qs[(r0 + 8) * 32 + (cs ^ 4)];
                #pragma unroll
                for (int jn = 0; jn < 8; jn++) {
                    unsigned b0 = K[(8 * jn + g) * 32 + cs];
                    unsigned b1 = K[(8 * jn + g) * 32 + (cs ^ 4)];
                    mma16(s[jn][0], s[jn][1], s[jn][2], s[jn][3],
                          a0, a1, a2, a3, b0, b1);
                }
            }

            // ---- causal mask (only when block intersects diagonal) ----
            const bool need_mask = (jb * 64 + 63) > wminrow;
            if (need_mask) {
                #pragma unroll
                for (int hf = 0; hf < 2; hf++) {
                    int trow = wminrow + 8 * hf + g;
                    #pragma unroll
                    for (int jn = 0; jn < 8; jn++) {
                        #pragma unroll
                        for (int e = 0; e < 2; e++) {
                            int col = jb * 64 + 8 * jn + 2 * qd + e;
                            if (col > trow) s[jn][2 * hf + e] = -1e30f;
                        }
                    }
                }
            }

            // ---- online softmax (base-2 domain) ----
            #pragma unroll
            for (int hf = 0; hf < 2; hf++) {
                float rmax = -1e30f;
                #pragma unroll
                for (int jn = 0; jn < 8; jn++) {
                    rmax = fmaxf(rmax, fmaxf(s[jn][2 * hf], s[jn][2 * hf + 1]));
                }
                rmax = fmaxf(rmax, __shfl_xor_sync(0xffffffffu, rmax, 1));
                rmax = fmaxf(rmax, __shfl_xor_sync(0xffffffffu, rmax, 2));
                float mnew = fmaxf(row_max[hf], rmax);
                float corr = ex2f(row_max[hf] - mnew);
                row_max[hf] = mnew;
                float psum = 0.f;
                #pragma unroll
                for (int jn = 0; jn < 8; jn++) {
                    #pragma unroll
                    for (int e = 0; e < 2; e++) {
                        float p = ex2f(s[jn][2 * hf + e] - mnew);
                        s[jn][2 * hf + e] = p;
                        psum += p;
                    }
                }
                psum += __shfl_xor_sync(0xffffffffu, psum, 1);
                psum += __shfl_xor_sync(0xffffffffu, psum, 2);
                row_sum[hf] = row_sum[hf] * corr + psum;
                #pragma unroll
                for (int jn = 0; jn < 8; jn++) {
                    o[jn][2 * hf + 0] *= corr;
                    o[jn][2 * hf + 1] *= corr;
                }
            }

            // ---- O += P V  (P fragment = repacked accumulator, no shuffles) ----
            #pragma unroll
            for (int ks = 0; ks < 4; ++ks) {
                unsigned pa0 = packh2(s[2 * ks][0],     s[2 * ks][1]);
                unsigned pa1 = packh2(s[2 * ks][2],     s[2 * ks][3]);
                unsigned pa2 = packh2(s[2 * ks + 1][0], s[2 * ks + 1][1]);
                unsigned pa3 = packh2(s[2 * ks + 1][2], s[2 * ks + 1][3]);

                // V B-fragments via ldmatrix.x4.trans, 2 jn per call
                unsigned vb[4][4];
                #pragma unroll
                for (int jnp = 0; jnp < 4; jnp++) {
                    int vrow = 16 * ks + vrow_off;
                    int wc = (4 * (2 * jnp + (lmat >> 1))) ^ vswz;
                    unsigned addr = vb32 + (vrow * 32 + wc) * 4;
                    asm volatile(
                        "ldmatrix.sync.aligned.m8n8.x4.trans.shared.b16 {%0,%1,%2,%3}, [%4];"
                        : "=r"(vb[jnp][0]), "=r"(vb[jnp][1]), "=r"(vb[jnp][2]), "=r"(vb[jnp][3])
                        : "r"(addr));
                }
                #pragma unroll
                for (int jn = 0; jn < 8; jn++) {
                    unsigned b0 = vb[jn >> 1][(jn & 1) * 2];
                    unsigned b1 = vb[jn >> 1][(jn & 1) * 2 + 1];
                    mma16(o[jn][0], o[jn][1], o[jn][2], o[jn][3],
                          pa0, pa1, pa2, pa3, b0, b1);
                }
            }
        }
    }

    // ---- normalize + store fp16 to g_atth [B][T][384] ----
    float inv0 = 1.0f / row_sum[0];
    float inv1 = 1.0f / row_sum[1];
    int trow = half * 128 + 16 * w + g;
    #pragma unroll
    for (int jn = 0; jn < 8; jn++) {
        int wdd = h * 32 + 4 * jn + qd;
        g_atth[(size_t)(b * TT + trow) * CW + wdd]       = packh2(o[jn][0] * inv0, o[jn][1] * inv0);
        g_atth[(size_t)(b * TT + trow + 8) * CW + wdd]   = packh2(o[jn][2] * inv1, o[jn][3] * inv1);
    }
}

// ---------------------------------------------------------------------------
extern "C" void kernel_launch(void* const* d_in, const int* in_sizes, int n_in,
                              void* d_out, int out_size)
{
    const float* x  = (const float*)d_in[0];
    const float* Wq = (const float*)d_in[1];
    const float* Wk = (const float*)d_in[2];
    const float* Wv = (const float*)d_in[3];
    const float* Wp = (const float*)d_in[4];
    const float* bp = (const float*)d_in[5];
    float* out = (float*)d_out;

    static bool attr_set = false;
    const int gemm_smem = 4 * STGW * 4;     // 73728 B
    if (!attr_set) {
        cudaFuncSetAttribute(qkv_gemm_kernel,  cudaFuncAttributeMaxDynamicSharedMemorySize, gemm_smem);
        cudaFuncSetAttribute(proj_gemm_kernel, cudaFuncAttributeMaxDynamicSharedMemorySize, gemm_smem);
        cudaFuncSetAttribute(attn_kernel,      cudaFuncAttributeMaxDynamicSharedMemorySize, ATTN_SMEM);
        attr_set = true;
    }

    prep_kernel<<<NCONV + NPACK, 256>>>(x, Wq, Wk, Wv, Wp);
    qkv_gemm_kernel<<<dim3(9, 256), 256, gemm_smem>>>();
    attn_kernel<<<dim3(BB * HH, 2), 256, ATTN_SMEM>>>();
    proj_gemm_kernel<<<dim3(3, 256), 256, gemm_smem>>>(bp, out);
}